// round 5
// baseline (speedup 1.0000x reference)
#include <cuda_runtime.h>

// Layout constants (columns within the 208-wide feature dim)
#define NCOLS        208
#define OPCODE_START 88
#define AX_START     163
#define PC_START     171
#define IMM_START    195
#define BRANCH_TAKEN 203
// opcode offsets
#define OP_JMP 2
#define OP_BZ  4
#define OP_BNZ 5

__device__ unsigned g_flags;

__global__ void reset_flags_kernel() {
    g_flags = 0u;
}

// One thread per row: check the three opcode columns, OR into global flags.
// Warp-level reduce first so we do ~1 atomic per warp, not per lane.
__global__ void scan_flags_kernel(const float* __restrict__ x, int nrows) {
    int stride = gridDim.x * blockDim.x;
    unsigned f = 0u;
    for (int r = blockIdx.x * blockDim.x + threadIdx.x; r < nrows; r += stride) {
        const float* xr = x + (size_t)r * NCOLS + OPCODE_START;
        if (xr[OP_JMP] > 0.5f) f |= 1u;
        if (xr[OP_BZ]  > 0.5f) f |= 2u;
        if (xr[OP_BNZ] > 0.5f) f |= 4u;
    }
    f = __reduce_or_sync(0xFFFFFFFFu, f);
    if ((threadIdx.x & 31) == 0 && f)
        atomicOr(&g_flags, f);
}

// One warp per row. Coalesced float4 copy of the whole row; lanes holding the
// PC-nibble chunks (42,43,44 -> v1 lanes 10,11,12) and the branch-taken chunk
// (50 -> v1 lane 18) patch their registers before storing.
__global__ void __launch_bounds__(256) apply_kernel(const float* __restrict__ x,
                                                    float* __restrict__ y,
                                                    int nrows) {
    int gw   = (blockIdx.x * blockDim.x + threadIdx.x) >> 5;
    int lane = threadIdx.x & 31;
    if (gw >= nrows) return;

    const float*  xr = x + (size_t)gw * NCOLS;
    float*        yr = y + (size_t)gw * NCOLS;
    const float4* xv = (const float4*)xr;
    float4*       yv = (float4*)yr;

    // Bulk row copy: 52 float4 chunks (208 floats).
    float4 v0 = xv[lane];
    float4 v1;
    if (lane < 20) v1 = xv[32 + lane];

    unsigned flags = g_flags;

    if (flags != 0u) {
        // Gather the 24 operand floats on lanes 0..7 (extra scalar loads hit
        // in L1 — the warp already pulled these lines for the copy).
        float a_l = 0.f, p_l = 0.f, i_l = 0.f;
        if (lane < 8) {
            a_l = xr[AX_START  + lane];
            p_l = xr[PC_START  + lane];
            i_l = xr[IMM_START + lane];
        }

        // Sequential n=0..7 accumulation to mirror XLA's unrolled contraction.
        // 16^n is a power of two -> the multiply is exact; only the add rounds,
        // so accumulation order is the single thing that must match.
        float imm = 0.f, pc = 0.f;
        int   ax  = 0;
        #pragma unroll
        for (int n = 0; n < 8; n++) {
            float an = __shfl_sync(0xFFFFFFFFu, a_l, n);
            float pn = __shfl_sync(0xFFFFFFFFu, p_l, n);
            float in_ = __shfl_sync(0xFFFFFFFFu, i_l, n);
            float pw = (float)(1 << (4 * n));
            imm = __fadd_rn(imm, __fmul_rn(in_, pw));
            pc  = __fadd_rn(pc,  __fmul_rn(pn,  pw));
            ax += (int)an * (1 << (4 * n));   // trunc-toward-zero == astype(int32)
        }

        bool jmp = (flags & 1u) != 0u;
        bool bz  = (flags & 2u) != 0u;
        bool bnz = (flags & 4u) != 0u;
        bool az  = (ax == 0);

        float new_pc, bt;
        float pc8 = __fadd_rn(pc, 8.0f);
        if (jmp)      { new_pc = imm;              bt = 1.0f; }
        else if (bz)  { new_pc = az ? imm : pc8;   bt = az ? 1.0f : 0.0f; }
        else if (bnz) { new_pc = az ? pc8 : imm;   bt = az ? 0.0f : 1.0f; }
        else          { new_pc = pc;               bt = v1.w; /* unreachable: flags!=0 */ }

        int v = (int)new_pc;  // round-toward-zero, matches astype(int32)

        // Patch PC nibbles: cols 171..178 live in chunks 42(e3), 43(e0..3), 44(e0..2)
        if (lane == 10) {           // chunk 42: col 171 = nib0
            v1.w = (float)(v & 15);
        } else if (lane == 11) {    // chunk 43: cols 172..175 = nib1..4
            v1.x = (float)((v >> 4)  & 15);
            v1.y = (float)((v >> 8)  & 15);
            v1.z = (float)((v >> 12) & 15);
            v1.w = (float)((v >> 16) & 15);
        } else if (lane == 12) {    // chunk 44: cols 176..178 = nib5..7
            v1.x = (float)((v >> 20) & 15);
            v1.y = (float)((v >> 24) & 15);
            v1.z = (float)((v >> 28) & 15);
        } else if (lane == 18) {    // chunk 50: col 203 = branch_taken
            v1.w = bt;
        }
    }
    // flags == 0: verbatim copy (reference early-return)

    yv[lane] = v0;
    if (lane < 20) yv[32 + lane] = v1;
}

extern "C" void kernel_launch(void* const* d_in, const int* in_sizes, int n_in,
                              void* d_out, int out_size) {
    const float* x = (const float*)d_in[0];
    float*       y = (float*)d_out;
    int nrows = in_sizes[0] / NCOLS;

    reset_flags_kernel<<<1, 1>>>();

    {
        int threads = 256;
        int blocks  = (nrows + threads - 1) / threads;
        if (blocks > 1024) blocks = 1024;   // grid-stride
        scan_flags_kernel<<<blocks, threads>>>(x, nrows);
    }

    {
        int threads = 256;                       // 8 warps/block = 8 rows/block
        int rows_per_block = threads / 32;
        int blocks = (nrows + rows_per_block - 1) / rows_per_block;
        apply_kernel<<<blocks, threads>>>(x, y, nrows);
    }
}

// round 6
// speedup vs baseline: 1.0070x; 1.0070x over previous
#include <cuda_runtime.h>

// Layout constants (columns within the 208-wide feature dim)
#define NCOLS        208
#define OPCODE_START 88
#define AX_START     163
#define PC_START     171
#define IMM_START    195
#define BRANCH_TAKEN 203
// opcode offsets
#define OP_JMP 2
#define OP_BZ  4
#define OP_BNZ 5

__device__ unsigned g_flags;

__global__ void reset_flags_kernel() {
    g_flags = 0u;
}

// One thread per row: check the three opcode columns, OR into global flags.
// Warp-level reduce first so we do ~1 atomic per warp, not per lane.
__global__ void scan_flags_kernel(const float* __restrict__ x, int nrows) {
    int stride = gridDim.x * blockDim.x;
    unsigned f = 0u;
    for (int r = blockIdx.x * blockDim.x + threadIdx.x; r < nrows; r += stride) {
        const float* xr = x + (size_t)r * NCOLS + OPCODE_START;
        if (xr[OP_JMP] > 0.5f) f |= 1u;
        if (xr[OP_BZ]  > 0.5f) f |= 2u;
        if (xr[OP_BNZ] > 0.5f) f |= 4u;
    }
    f = __reduce_or_sync(0xFFFFFFFFu, f);
    if ((threadIdx.x & 31) == 0 && f)
        atomicOr(&g_flags, f);
}

// One warp per row. Coalesced float4 copy of the whole row; lanes holding the
// PC-nibble chunks (42,43,44 -> v1 lanes 10,11,12) and the branch-taken chunk
// (50 -> v1 lane 18) patch their registers before storing.
__global__ void __launch_bounds__(256) apply_kernel(const float* __restrict__ x,
                                                    float* __restrict__ y,
                                                    int nrows) {
    int gw   = (blockIdx.x * blockDim.x + threadIdx.x) >> 5;
    int lane = threadIdx.x & 31;
    if (gw >= nrows) return;

    const float*  xr = x + (size_t)gw * NCOLS;
    float*        yr = y + (size_t)gw * NCOLS;
    const float4* xv = (const float4*)xr;
    float4*       yv = (float4*)yr;

    // Bulk row copy: 52 float4 chunks (208 floats).
    float4 v0 = xv[lane];
    float4 v1;
    if (lane < 20) v1 = xv[32 + lane];

    unsigned flags = g_flags;

    if (flags != 0u) {
        // Gather the 24 operand floats on lanes 0..7 (extra scalar loads hit
        // in L1 — the warp already pulled these lines for the copy).
        float a_l = 0.f, p_l = 0.f, i_l = 0.f;
        if (lane < 8) {
            a_l = xr[AX_START  + lane];
            p_l = xr[PC_START  + lane];
            i_l = xr[IMM_START + lane];
        }

        // Sequential n=0..7 accumulation to mirror XLA's unrolled contraction.
        // 16^n is a power of two -> the multiply is exact; only the add rounds,
        // so accumulation order is the single thing that must match.
        float imm = 0.f, pc = 0.f;
        int   ax  = 0;
        #pragma unroll
        for (int n = 0; n < 8; n++) {
            float an = __shfl_sync(0xFFFFFFFFu, a_l, n);
            float pn = __shfl_sync(0xFFFFFFFFu, p_l, n);
            float in_ = __shfl_sync(0xFFFFFFFFu, i_l, n);
            float pw = (float)(1 << (4 * n));
            imm = __fadd_rn(imm, __fmul_rn(in_, pw));
            pc  = __fadd_rn(pc,  __fmul_rn(pn,  pw));
            ax += (int)an * (1 << (4 * n));   // trunc-toward-zero == astype(int32)
        }

        bool jmp = (flags & 1u) != 0u;
        bool bz  = (flags & 2u) != 0u;
        bool bnz = (flags & 4u) != 0u;
        bool az  = (ax == 0);

        float new_pc, bt;
        float pc8 = __fadd_rn(pc, 8.0f);
        if (jmp)      { new_pc = imm;              bt = 1.0f; }
        else if (bz)  { new_pc = az ? imm : pc8;   bt = az ? 1.0f : 0.0f; }
        else if (bnz) { new_pc = az ? pc8 : imm;   bt = az ? 0.0f : 1.0f; }
        else          { new_pc = pc;               bt = v1.w; /* unreachable: flags!=0 */ }

        int v = (int)new_pc;  // round-toward-zero, matches astype(int32)

        // Patch PC nibbles: cols 171..178 live in chunks 42(e3), 43(e0..3), 44(e0..2)
        if (lane == 10) {           // chunk 42: col 171 = nib0
            v1.w = (float)(v & 15);
        } else if (lane == 11) {    // chunk 43: cols 172..175 = nib1..4
            v1.x = (float)((v >> 4)  & 15);
            v1.y = (float)((v >> 8)  & 15);
            v1.z = (float)((v >> 12) & 15);
            v1.w = (float)((v >> 16) & 15);
        } else if (lane == 12) {    // chunk 44: cols 176..178 = nib5..7
            v1.x = (float)((v >> 20) & 15);
            v1.y = (float)((v >> 24) & 15);
            v1.z = (float)((v >> 28) & 15);
        } else if (lane == 18) {    // chunk 50: col 203 = branch_taken
            v1.w = bt;
        }
    }
    // flags == 0: verbatim copy (reference early-return)

    yv[lane] = v0;
    if (lane < 20) yv[32 + lane] = v1;
}

extern "C" void kernel_launch(void* const* d_in, const int* in_sizes, int n_in,
                              void* d_out, int out_size) {
    const float* x = (const float*)d_in[0];
    float*       y = (float*)d_out;
    int nrows = in_sizes[0] / NCOLS;

    reset_flags_kernel<<<1, 1>>>();

    {
        int threads = 256;
        int blocks  = (nrows + threads - 1) / threads;
        if (blocks > 1024) blocks = 1024;   // grid-stride
        scan_flags_kernel<<<blocks, threads>>>(x, nrows);
    }

    {
        int threads = 256;                       // 8 warps/block = 8 rows/block
        int rows_per_block = threads / 32;
        int blocks = (nrows + rows_per_block - 1) / rows_per_block;
        apply_kernel<<<blocks, threads>>>(x, y, nrows);
    }
}

// round 7
// speedup vs baseline: 1.0181x; 1.0110x over previous
#include <cuda_runtime.h>

// Layout constants (columns within the 208-wide feature dim)
#define NCOLS        208
#define OPCODE_START 88
#define AX_START     163
#define PC_START     171
#define IMM_START    195
#define BRANCH_TAKEN 203
// opcode offsets
#define OP_JMP 2
#define OP_BZ  4
#define OP_BNZ 5

__device__ unsigned g_flags;

__global__ void reset_flags_kernel() {
    g_flags = 0u;
}

// One thread per row: check the three opcode columns, OR into global flags.
// Warp-level reduce first so we do ~1 atomic per warp, not per lane.
__global__ void scan_flags_kernel(const float* __restrict__ x, int nrows) {
    int stride = gridDim.x * blockDim.x;
    unsigned f = 0u;
    for (int r = blockIdx.x * blockDim.x + threadIdx.x; r < nrows; r += stride) {
        const float* xr = x + (size_t)r * NCOLS + OPCODE_START;
        if (xr[OP_JMP] > 0.5f) f |= 1u;
        if (xr[OP_BZ]  > 0.5f) f |= 2u;
        if (xr[OP_BNZ] > 0.5f) f |= 4u;
    }
    f = __reduce_or_sync(0xFFFFFFFFu, f);
    if ((threadIdx.x & 31) == 0 && f)
        atomicOr(&g_flags, f);
}

// One warp per row. Coalesced float4 copy of the whole row; lanes holding the
// PC-nibble chunks (42,43,44 -> v1 lanes 10,11,12) and the branch-taken chunk
// (50 -> v1 lane 18) patch their registers before storing.
__global__ void __launch_bounds__(256) apply_kernel(const float* __restrict__ x,
                                                    float* __restrict__ y,
                                                    int nrows) {
    int gw   = (blockIdx.x * blockDim.x + threadIdx.x) >> 5;
    int lane = threadIdx.x & 31;
    if (gw >= nrows) return;

    const float*  xr = x + (size_t)gw * NCOLS;
    float*        yr = y + (size_t)gw * NCOLS;
    const float4* xv = (const float4*)xr;
    float4*       yv = (float4*)yr;

    // Bulk row copy: 52 float4 chunks (208 floats).
    float4 v0 = xv[lane];
    float4 v1;
    if (lane < 20) v1 = xv[32 + lane];

    unsigned flags = g_flags;

    if (flags != 0u) {
        // Gather the 24 operand floats on lanes 0..7 (extra scalar loads hit
        // in L1 — the warp already pulled these lines for the copy).
        float a_l = 0.f, p_l = 0.f, i_l = 0.f;
        if (lane < 8) {
            a_l = xr[AX_START  + lane];
            p_l = xr[PC_START  + lane];
            i_l = xr[IMM_START + lane];
        }

        // Sequential n=0..7 accumulation to mirror XLA's unrolled contraction.
        // 16^n is a power of two -> the multiply is exact; only the add rounds,
        // so accumulation order is the single thing that must match.
        float imm = 0.f, pc = 0.f;
        int   ax  = 0;
        #pragma unroll
        for (int n = 0; n < 8; n++) {
            float an = __shfl_sync(0xFFFFFFFFu, a_l, n);
            float pn = __shfl_sync(0xFFFFFFFFu, p_l, n);
            float in_ = __shfl_sync(0xFFFFFFFFu, i_l, n);
            float pw = (float)(1 << (4 * n));
            imm = __fadd_rn(imm, __fmul_rn(in_, pw));
            pc  = __fadd_rn(pc,  __fmul_rn(pn,  pw));
            ax += (int)an * (1 << (4 * n));   // trunc-toward-zero == astype(int32)
        }

        bool jmp = (flags & 1u) != 0u;
        bool bz  = (flags & 2u) != 0u;
        bool bnz = (flags & 4u) != 0u;
        bool az  = (ax == 0);

        float new_pc, bt;
        float pc8 = __fadd_rn(pc, 8.0f);
        if (jmp)      { new_pc = imm;              bt = 1.0f; }
        else if (bz)  { new_pc = az ? imm : pc8;   bt = az ? 1.0f : 0.0f; }
        else if (bnz) { new_pc = az ? pc8 : imm;   bt = az ? 0.0f : 1.0f; }
        else          { new_pc = pc;               bt = v1.w; /* unreachable: flags!=0 */ }

        int v = (int)new_pc;  // round-toward-zero, matches astype(int32)

        // Patch PC nibbles: cols 171..178 live in chunks 42(e3), 43(e0..3), 44(e0..2)
        if (lane == 10) {           // chunk 42: col 171 = nib0
            v1.w = (float)(v & 15);
        } else if (lane == 11) {    // chunk 43: cols 172..175 = nib1..4
            v1.x = (float)((v >> 4)  & 15);
            v1.y = (float)((v >> 8)  & 15);
            v1.z = (float)((v >> 12) & 15);
            v1.w = (float)((v >> 16) & 15);
        } else if (lane == 12) {    // chunk 44: cols 176..178 = nib5..7
            v1.x = (float)((v >> 20) & 15);
            v1.y = (float)((v >> 24) & 15);
            v1.z = (float)((v >> 28) & 15);
        } else if (lane == 18) {    // chunk 50: col 203 = branch_taken
            v1.w = bt;
        }
    }
    // flags == 0: verbatim copy (reference early-return)

    yv[lane] = v0;
    if (lane < 20) yv[32 + lane] = v1;
}

extern "C" void kernel_launch(void* const* d_in, const int* in_sizes, int n_in,
                              void* d_out, int out_size) {
    const float* x = (const float*)d_in[0];
    float*       y = (float*)d_out;
    int nrows = in_sizes[0] / NCOLS;

    reset_flags_kernel<<<1, 1>>>();

    {
        int threads = 256;
        int blocks  = (nrows + threads - 1) / threads;
        if (blocks > 1024) blocks = 1024;   // grid-stride
        scan_flags_kernel<<<blocks, threads>>>(x, nrows);
    }

    {
        int threads = 256;                       // 8 warps/block = 8 rows/block
        int rows_per_block = threads / 32;
        int blocks = (nrows + rows_per_block - 1) / rows_per_block;
        apply_kernel<<<blocks, threads>>>(x, y, nrows);
    }
}